// round 10
// baseline (speedup 1.0000x reference)
#include <cuda_runtime.h>

// ---------------- problem constants ----------------
constexpr int Bb = 4, Tt = 2048, Ssq = 2048, Ee = 512, Hh = 8, Dd = 64;
constexpr int BT = Bb * Tt;

// ---------------- device scratch (no cudaMalloc allowed) ----------------
__device__ float g_q[(size_t)Bb * Hh * Tt * Dd];       // [B,H,T,64], pre-scaled
__device__ float g_k[(size_t)Bb * Hh * Ssq * Dd];      // [B,H,S,64]
__device__ float g_v[(size_t)Bb * Hh * Ssq * Dd];      // [B,H,S,64]
__device__ float g_attnout[(size_t)BT * Ee];           // [B,T,E] pre-output-proj
__device__ float g_rowm[(size_t)Bb * Hh * Tt];         // per-row softmax max
__device__ float g_rowl[(size_t)Bb * Hh * Tt];         // per-row softmax denom

// ---------------- SGEMM: C = A[M,K] @ W[K,N] + bias, optional head layout ----------------
constexpr int BM = 128, BN = 128, BKk = 8, TM = 8, TN = 8;

__global__ __launch_bounds__(256, 2) void sgemm_bias(
    const float* __restrict__ A, const float* __restrict__ W,
    const float* __restrict__ bias, float* __restrict__ C,
    float scale, int head_layout)
{
    __shared__ float As[BKk][BM];
    __shared__ float Ws[BKk][BN];
    const int K = Ee, N = Ee;
    const int tid  = threadIdx.x;
    const int tcol = tid & 15;        // 16 col-groups
    const int trow = tid >> 4;        // 16 row-groups
    const int aRow = tid >> 1;        // 0..127
    const int aCol = (tid & 1) * 4;   // 0 or 4
    const int wRow = tid >> 5;        // 0..7
    const int wCol = (tid & 31) * 4;  // 0..124

    const float* Ab = A + (size_t)blockIdx.y * BM * K;
    const float* Wb = W + blockIdx.x * BN;

    float acc[TM][TN];
#pragma unroll
    for (int i = 0; i < TM; i++)
#pragma unroll
        for (int j = 0; j < TN; j++) acc[i][j] = 0.f;

    for (int k0 = 0; k0 < K; k0 += BKk) {
        float4 av = *(const float4*)(Ab + (size_t)aRow * K + k0 + aCol);
        As[aCol + 0][aRow] = av.x;
        As[aCol + 1][aRow] = av.y;
        As[aCol + 2][aRow] = av.z;
        As[aCol + 3][aRow] = av.w;
        *(float4*)(&Ws[wRow][wCol]) = *(const float4*)(Wb + (size_t)(k0 + wRow) * N + wCol);
        __syncthreads();
#pragma unroll
        for (int k = 0; k < BKk; k++) {
            float4 a0 = *(const float4*)&As[k][trow * TM];
            float4 a1 = *(const float4*)&As[k][trow * TM + 4];
            float4 b0 = *(const float4*)&Ws[k][tcol * TN];
            float4 b1 = *(const float4*)&Ws[k][tcol * TN + 4];
            float ar[8] = {a0.x, a0.y, a0.z, a0.w, a1.x, a1.y, a1.z, a1.w};
            float br[8] = {b0.x, b0.y, b0.z, b0.w, b1.x, b1.y, b1.z, b1.w};
#pragma unroll
            for (int i = 0; i < TM; i++)
#pragma unroll
                for (int j = 0; j < TN; j++) acc[i][j] = fmaf(ar[i], br[j], acc[i][j]);
        }
        __syncthreads();
    }

#pragma unroll
    for (int i = 0; i < TM; i++) {
        int m = blockIdx.y * BM + trow * TM + i;
        int b = m / Tt, t = m % Tt;
#pragma unroll
        for (int j = 0; j < TN; j++) {
            int n = blockIdx.x * BN + tcol * TN + j;
            float v = (acc[i][j] + bias[n]) * scale;
            if (head_layout) {
                int h = n >> 6, d = n & 63;
                C[((size_t)(b * Hh + h) * Tt + t) * Dd + d] = v;
            } else {
                C[(size_t)m * N + n] = v;
            }
        }
    }
}

// ---------------- fused attention ----------------
// Natural [row][d] layouts with LD=68 (68/4 = 17, odd -> LDS.128 phases are
// bank-conflict-free). Score loop is float4 over d: 12 LDS.128 per 128 FMA
// (was 36 LDS ops). Ps aliases Ks (disjoint lifetimes). smem = 90112B -> 2 CTA/SM.
constexpr int QT = 64, SC = 128;
constexpr int Q_LD = 68, K_LD = 68, P_LD = 68, RED_LD = 17;
constexpr int KSPS_FLOATS = SC * K_LD;  // 8704 floats (Ks and Ps both fit)
constexpr int ATT_SMEM_FLOATS =
    QT * Q_LD + KSPS_FLOATS + SC * Dd + QT * RED_LD + 3 * QT;   // 22528 floats
constexpr int ATT_SMEM_BYTES = ATT_SMEM_FLOATS * 4;             // 90112 B

__global__ __launch_bounds__(256, 2) void attn_kernel(
    const unsigned char* __restrict__ kpm,    // [B,S] bool
    const unsigned char* __restrict__ amask,  // [T,S] bool
    float* __restrict__ attnw)                // raw-score scratch (may be null)
{
    extern __shared__ float sm[];
    float* Qs  = sm;                     // [QT][Q_LD]  natural layout
    float* Ks  = Qs + QT * Q_LD;         // [SC][K_LD]  natural layout
    float* Ps  = Ks;                     // [SC][P_LD]  ALIAS (s-major, row minor)
    float* Vs  = Ks + KSPS_FLOATS;       // [SC][Dd]
    float* red = Vs + SC * Dd;           // [QT][RED_LD]
    float* m_s = red + QT * RED_LD;      // [QT]
    float* l_s = m_s + QT;               // [QT]
    float* f_s = l_s + QT;               // [QT]

    const int b  = blockIdx.z, h = blockIdx.y;
    const int t0 = blockIdx.x * QT;
    const int tid = threadIdx.x;
    const int tx  = tid & 15, ty = tid >> 4;
    const int r   = tid >> 4;
    const int d4  = (tid & 15) * 4;

    const float* qptr  = g_q + ((size_t)(b * Hh + h) * Tt + t0) * Dd;
    const float* kbase = g_k + (size_t)(b * Hh + h) * Ssq * Dd;
    const float* vbase = g_v + (size_t)(b * Hh + h) * Ssq * Dd;
    const unsigned char* kpmb = kpm + (size_t)b * Ssq;

    // load Q tile (natural layout, straight float4 copy)
#pragma unroll
    for (int tt = r; tt < QT; tt += 16)
        *(float4*)&Qs[tt * Q_LD + d4] =
            *(const float4*)(qptr + (size_t)tt * Dd + d4);
    if (tid < QT) { m_s[tid] = -3.0e38f; l_s[tid] = 0.f; }

    // acc[i][j]: rows t0 + ty*4 + i, head dims tx*4 + j
    float acc[4][4];
#pragma unroll
    for (int i = 0; i < 4; i++)
#pragma unroll
        for (int j = 0; j < 4; j++) acc[i][j] = 0.f;

    for (int s0 = 0; s0 < Ssq; s0 += SC) {
        __syncthreads();  // previous iteration's Ps (alias of Ks) / Vs reads done
        // load K and V chunks (straight float4 copies, no transpose)
        for (int ssr = r; ssr < SC; ssr += 16) {
            *(float4*)&Ks[ssr * K_LD + d4] =
                *(const float4*)(kbase + (size_t)(s0 + ssr) * Dd + d4);
            *(float4*)&Vs[ssr * Dd + d4] =
                *(const float4*)(vbase + (size_t)(s0 + ssr) * Dd + d4);
        }
        __syncthreads();

        // scores: st[i][j] = sum_d q[t0+ty*4+i][d] * k[s0+tx+16j][d]
        float st[4][8];
#pragma unroll
        for (int i = 0; i < 4; i++)
#pragma unroll
            for (int j = 0; j < 8; j++) st[i][j] = 0.f;

#pragma unroll 4
        for (int d0 = 0; d0 < Dd; d0 += 4) {
            float4 q0 = *(const float4*)&Qs[(ty * 4 + 0) * Q_LD + d0];
            float4 q1 = *(const float4*)&Qs[(ty * 4 + 1) * Q_LD + d0];
            float4 q2 = *(const float4*)&Qs[(ty * 4 + 2) * Q_LD + d0];
            float4 q3 = *(const float4*)&Qs[(ty * 4 + 3) * Q_LD + d0];
#pragma unroll
            for (int j = 0; j < 8; j++) {
                float4 kv = *(const float4*)&Ks[(tx + 16 * j) * K_LD + d0];
                st[0][j] = fmaf(q0.x, kv.x, st[0][j]);
                st[0][j] = fmaf(q0.y, kv.y, st[0][j]);
                st[0][j] = fmaf(q0.z, kv.z, st[0][j]);
                st[0][j] = fmaf(q0.w, kv.w, st[0][j]);
                st[1][j] = fmaf(q1.x, kv.x, st[1][j]);
                st[1][j] = fmaf(q1.y, kv.y, st[1][j]);
                st[1][j] = fmaf(q1.z, kv.z, st[1][j]);
                st[1][j] = fmaf(q1.w, kv.w, st[1][j]);
                st[2][j] = fmaf(q2.x, kv.x, st[2][j]);
                st[2][j] = fmaf(q2.y, kv.y, st[2][j]);
                st[2][j] = fmaf(q2.z, kv.z, st[2][j]);
                st[2][j] = fmaf(q2.w, kv.w, st[2][j]);
                st[3][j] = fmaf(q3.x, kv.x, st[3][j]);
                st[3][j] = fmaf(q3.y, kv.y, st[3][j]);
                st[3][j] = fmaf(q3.z, kv.z, st[3][j]);
                st[3][j] = fmaf(q3.w, kv.w, st[3][j]);
            }
        }

        // masks
#pragma unroll
        for (int j = 0; j < 8; j++) {
            int sg = s0 + tx + 16 * j;
            bool km = kpmb[sg] != 0;
#pragma unroll
            for (int i = 0; i < 4; i++) {
                int tg = t0 + ty * 4 + i;
                if (km || amask[(size_t)tg * Ssq + sg]) st[i][j] = -1e30f;
            }
        }

        // store raw (masked) scores; normalized later
        if (attnw) {
#pragma unroll
            for (int i = 0; i < 4; i++) {
                size_t base =
                    ((size_t)((b * Hh + h) * Tt) + t0 + ty * 4 + i) * Ssq + s0 + tx;
#pragma unroll
                for (int j = 0; j < 8; j++) attnw[base + 16 * j] = st[i][j];
            }
        }

        // chunk row max
#pragma unroll
        for (int i = 0; i < 4; i++) {
            float mx = st[i][0];
#pragma unroll
            for (int j = 1; j < 8; j++) mx = fmaxf(mx, st[i][j]);
            red[(ty * 4 + i) * RED_LD + tx] = mx;
        }
        __syncthreads();   // also: last Ks reads complete before Ps overwrite below
        if (tid < QT) {
            float cm = red[tid * RED_LD];
#pragma unroll
            for (int x = 1; x < 16; x++) cm = fmaxf(cm, red[tid * RED_LD + x]);
            float mo = m_s[tid];
            float mn = fmaxf(mo, cm);
            float f  = __expf(mo - mn);
            m_s[tid] = mn; f_s[tid] = f; l_s[tid] *= f;
        }
        __syncthreads();

        // p = exp(s - m), rescale acc, partial row sums, stage P (into Ks alias)
#pragma unroll
        for (int i = 0; i < 4; i++) {
            int row = ty * 4 + i;
            float mn = m_s[row];
            float f  = f_s[row];
#pragma unroll
            for (int j = 0; j < 4; j++) acc[i][j] *= f;
            float s = 0.f;
#pragma unroll
            for (int j = 0; j < 8; j++) {
                float p = __expf(st[i][j] - mn);
                Ps[(tx + 16 * j) * P_LD + row] = p;
                s += p;
            }
            red[row * RED_LD + tx] = s;
        }
        __syncthreads();
        if (tid < QT) {
            float s = 0.f;
#pragma unroll
            for (int x = 0; x < 16; x++) s += red[tid * RED_LD + x];
            l_s[tid] += s;
        }

        // PV: acc[i][j] += P[t][s] * V[s][d], d = tx*4 + j — LDS.128 pairs
#pragma unroll 4
        for (int ss2 = 0; ss2 < SC; ss2++) {
            float4 pa = *(const float4*)&Ps[ss2 * P_LD + ty * 4];
            float4 vb = *(const float4*)&Vs[ss2 * Dd + tx * 4];
            float pr[4] = {pa.x, pa.y, pa.z, pa.w};
            float vr[4] = {vb.x, vb.y, vb.z, vb.w};
#pragma unroll
            for (int i = 0; i < 4; i++)
#pragma unroll
                for (int j = 0; j < 4; j++)
                    acc[i][j] = fmaf(pr[i], vr[j], acc[i][j]);
        }
    }

    __syncthreads();
#pragma unroll
    for (int i = 0; i < 4; i++) {
        int t = t0 + ty * 4 + i;
        float invl = 1.f / l_s[ty * 4 + i];
        size_t base = ((size_t)b * Tt + t) * Ee + h * Dd;
        float4 o;
        o.x = acc[i][0] * invl;
        o.y = acc[i][1] * invl;
        o.z = acc[i][2] * invl;
        o.w = acc[i][3] * invl;
        *(float4*)&g_attnout[base + tx * 4] = o;
    }
    if (tid < QT) {
        size_t row = (size_t)(b * Hh + h) * Tt + t0 + tid;
        g_rowm[row] = m_s[tid];
        g_rowl[row] = l_s[tid];
    }
}

// ---------------- normalize raw scores -> softmax weights, in place ----------------
__global__ void normalize_attn(float* __restrict__ attnw)
{
    const size_t n4 = (size_t)Bb * Hh * Tt * Ssq / 4;
    float4* a4 = (float4*)attnw;
    for (size_t i = (size_t)blockIdx.x * blockDim.x + threadIdx.x; i < n4;
         i += (size_t)gridDim.x * blockDim.x) {
        size_t row = (i * 4) / Ssq;
        float m = g_rowm[row];
        float invl = 1.f / g_rowl[row];
        float4 v = a4[i];
        v.x = __expf(v.x - m) * invl;
        v.y = __expf(v.y - m) * invl;
        v.z = __expf(v.z - m) * invl;
        v.w = __expf(v.w - m) * invl;
        a4[i] = v;
    }
}

// ---------------- launch ----------------
extern "C" void kernel_launch(void* const* d_in, const int* in_sizes, int n_in,
                              void* d_out, int out_size)
{
    const float* query = (const float*)d_in[0];
    const float* key   = (const float*)d_in[1];
    const float* value = (const float*)d_in[2];
    const unsigned char* kpm = (const unsigned char*)d_in[3];
    const unsigned char* am  = (const unsigned char*)d_in[4];
    const float* Wq = (const float*)d_in[5];  const float* bq = (const float*)d_in[6];
    const float* Wk = (const float*)d_in[7];  const float* bk = (const float*)d_in[8];
    const float* Wv = (const float*)d_in[9];  const float* bv = (const float*)d_in[10];
    const float* Wo = (const float*)d_in[11]; const float* bo = (const float*)d_in[12];

    float *qp, *kp, *vp, *aop;
    cudaGetSymbolAddress((void**)&qp,  g_q);
    cudaGetSymbolAddress((void**)&kp,  g_k);
    cudaGetSymbolAddress((void**)&vp,  g_v);
    cudaGetSymbolAddress((void**)&aop, g_attnout);

    const long long OUT_E  = (long long)Bb * Tt * Ee;                  // 4,194,304
    const long long ATTN_E = (long long)Bb * Hh * Tt * (long long)Ssq; // 134,217,728
    float* out_main = nullptr;
    float* out_attn = nullptr;
    if ((long long)out_size >= OUT_E + ATTN_E) {
        out_main = (float*)d_out;
        out_attn = (float*)d_out + OUT_E;
    } else if ((long long)out_size == ATTN_E) {
        out_attn = (float*)d_out;
    } else {
        out_main = (float*)d_out;
    }

    dim3 pg(Ee / BN, BT / BM);  // (4, 64)

    // projections (head-split layout; Q pre-scaled by Dh^-0.5)
    sgemm_bias<<<pg, 256>>>(query, Wq, bq, qp, 0.125f, 1);
    sgemm_bias<<<pg, 256>>>(key,   Wk, bk, kp, 1.0f,   1);
    sgemm_bias<<<pg, 256>>>(value, Wv, bv, vp, 1.0f,   1);

    // fused attention (2 CTAs/SM; conflict-free LDS.128 throughout)
    cudaFuncSetAttribute(attn_kernel, cudaFuncAttributeMaxDynamicSharedMemorySize,
                         ATT_SMEM_BYTES);
    dim3 ag(Tt / QT, Hh, Bb);  // (32, 8, 4)
    attn_kernel<<<ag, 256, ATT_SMEM_BYTES>>>(kpm, am, out_attn);

    if (out_attn) normalize_attn<<<2048, 256>>>(out_attn);

    if (out_main) sgemm_bias<<<pg, 256>>>(aop, Wo, bo, out_main, 1.0f, 0);
}

// round 11
// speedup vs baseline: 1.4165x; 1.4165x over previous
#include <cuda_runtime.h>
#include <cuda_bf16.h>

// ---------------- problem constants ----------------
constexpr int Bb = 4, Tt = 2048, Ssq = 2048, Ee = 512, Hh = 8, Dd = 64;
constexpr int BT = Bb * Tt;

// ---------------- device scratch (no cudaMalloc allowed) ----------------
__device__ float g_q[(size_t)Bb * Hh * Tt * Dd];       // [B,H,T,64], pre-scaled
__device__ float g_k[(size_t)Bb * Hh * Ssq * Dd];      // [B,H,S,64]
__device__ float g_v[(size_t)Bb * Hh * Ssq * Dd];      // [B,H,S,64]
__device__ float g_attnout[(size_t)BT * Ee];           // [B,T,E] pre-output-proj
__device__ float g_rowm[(size_t)Bb * Hh * Tt];         // per-row softmax max
__device__ float g_rowl[(size_t)Bb * Hh * Tt];         // per-row softmax denom

// ---------------- SGEMM: C = A[M,K] @ W[K,N] + bias, optional head layout ----------------
constexpr int BM = 128, BN = 128, BKk = 8, TM = 8, TN = 8;

__global__ __launch_bounds__(256, 2) void sgemm_bias(
    const float* __restrict__ A, const float* __restrict__ W,
    const float* __restrict__ bias, float* __restrict__ C,
    float scale, int head_layout)
{
    __shared__ float As[BKk][BM];
    __shared__ float Ws[BKk][BN];
    const int K = Ee, N = Ee;
    const int tid  = threadIdx.x;
    const int tcol = tid & 15;
    const int trow = tid >> 4;
    const int aRow = tid >> 1;
    const int aCol = (tid & 1) * 4;
    const int wRow = tid >> 5;
    const int wCol = (tid & 31) * 4;

    const float* Ab = A + (size_t)blockIdx.y * BM * K;
    const float* Wb = W + blockIdx.x * BN;

    float acc[TM][TN];
#pragma unroll
    for (int i = 0; i < TM; i++)
#pragma unroll
        for (int j = 0; j < TN; j++) acc[i][j] = 0.f;

    for (int k0 = 0; k0 < K; k0 += BKk) {
        float4 av = *(const float4*)(Ab + (size_t)aRow * K + k0 + aCol);
        As[aCol + 0][aRow] = av.x;
        As[aCol + 1][aRow] = av.y;
        As[aCol + 2][aRow] = av.z;
        As[aCol + 3][aRow] = av.w;
        *(float4*)(&Ws[wRow][wCol]) = *(const float4*)(Wb + (size_t)(k0 + wRow) * N + wCol);
        __syncthreads();
#pragma unroll
        for (int k = 0; k < BKk; k++) {
            float4 a0 = *(const float4*)&As[k][trow * TM];
            float4 a1 = *(const float4*)&As[k][trow * TM + 4];
            float4 b0 = *(const float4*)&Ws[k][tcol * TN];
            float4 b1 = *(const float4*)&Ws[k][tcol * TN + 4];
            float ar[8] = {a0.x, a0.y, a0.z, a0.w, a1.x, a1.y, a1.z, a1.w};
            float br[8] = {b0.x, b0.y, b0.z, b0.w, b1.x, b1.y, b1.z, b1.w};
#pragma unroll
            for (int i = 0; i < TM; i++)
#pragma unroll
                for (int j = 0; j < TN; j++) acc[i][j] = fmaf(ar[i], br[j], acc[i][j]);
        }
        __syncthreads();
    }

#pragma unroll
    for (int i = 0; i < TM; i++) {
        int m = blockIdx.y * BM + trow * TM + i;
        int b = m / Tt, t = m % Tt;
#pragma unroll
        for (int j = 0; j < TN; j++) {
            int n = blockIdx.x * BN + tcol * TN + j;
            float v = (acc[i][j] + bias[n]) * scale;
            if (head_layout) {
                int h = n >> 6, d = n & 63;
                C[((size_t)(b * Hh + h) * Tt + t) * Dd + d] = v;
            } else {
                C[(size_t)m * N + n] = v;
            }
        }
    }
}

// ================= tensor-core fused attention =================
// CTA = 128 q rows (8 warps x m16), S chunks of 64.
// QK^T and PV on mma.sync.m16n8k16 bf16 with 2-term splits (hi+lo):
//   a*b ~= ah*bh + ah*bl + al*bh  (error ~2^-16, fp32-grade)
// Softmax stats are warp-local (each warp owns its 16 rows).

constexpr int AQT = 128;   // q rows per CTA
constexpr int ASC = 64;    // s chunk
constexpr int KW  = 36;    // u32 words per smem row (72 bf16, conflict-free)

__device__ __forceinline__ void mma_bf16(float c[4],
    unsigned a0, unsigned a1, unsigned a2, unsigned a3,
    unsigned b0, unsigned b1)
{
    asm volatile(
        "mma.sync.aligned.m16n8k16.row.col.f32.bf16.bf16.f32 "
        "{%0,%1,%2,%3}, {%4,%5,%6,%7}, {%8,%9}, {%0,%1,%2,%3};"
        : "+f"(c[0]), "+f"(c[1]), "+f"(c[2]), "+f"(c[3])
        : "r"(a0), "r"(a1), "r"(a2), "r"(a3), "r"(b0), "r"(b1));
}

__device__ __forceinline__ void split_pack(float x, float y,
                                           unsigned& hi, unsigned& lo)
{
    __nv_bfloat162 h = __floats2bfloat162_rn(x, y);     // x -> low, y -> high
    float hx = __bfloat162float(__low2bfloat16(h));
    float hy = __bfloat162float(__high2bfloat16(h));
    __nv_bfloat162 l2 = __floats2bfloat162_rn(x - hx, y - hy);
    hi = *reinterpret_cast<unsigned*>(&h);
    lo = *reinterpret_cast<unsigned*>(&l2);
}

__global__ __launch_bounds__(256, 1) void attn_kernel(
    const unsigned char* __restrict__ kpm,    // [B,S] bool
    const unsigned char* __restrict__ amask,  // [T,S] bool
    float* __restrict__ attnw)                // raw-score scratch (may be null)
{
    __shared__ unsigned sKhi[ASC * KW];
    __shared__ unsigned sKlo[ASC * KW];
    __shared__ unsigned sVhi[Dd * KW];   // V transposed: [d][s]
    __shared__ unsigned sVlo[Dd * KW];

    const int b  = blockIdx.z, h = blockIdx.y;
    const int t0 = blockIdx.x * AQT;
    const int tid = threadIdx.x;
    const int w   = tid >> 5;
    const int l   = tid & 31;
    const int lq  = l >> 2;     // l/4  (row within fragment / n index)
    const int lr  = l & 3;      // l%4  (col pair index)

    const float* qbase = g_q + (size_t)(b * Hh + h) * Tt * Dd;
    const float* kbase = g_k + (size_t)(b * Hh + h) * Ssq * Dd;
    const float* vbase = g_v + (size_t)(b * Hh + h) * Ssq * Dd;
    const unsigned char* kpmb = kpm + (size_t)b * Ssq;

    const int rg0 = t0 + 16 * w + lq;       // global q row (first half)
    const int rg1 = rg0 + 8;                // second half

    // ---- Q A-fragments (hi/lo), loaded once ----
    unsigned qa_hi[4][4], qa_lo[4][4];
#pragma unroll
    for (int kt = 0; kt < 4; kt++) {
        int c = 16 * kt + 2 * lr;
        float2 q00 = *(const float2*)(qbase + (size_t)rg0 * Dd + c);
        float2 q10 = *(const float2*)(qbase + (size_t)rg1 * Dd + c);
        float2 q01 = *(const float2*)(qbase + (size_t)rg0 * Dd + c + 8);
        float2 q11 = *(const float2*)(qbase + (size_t)rg1 * Dd + c + 8);
        split_pack(q00.x, q00.y, qa_hi[kt][0], qa_lo[kt][0]);
        split_pack(q10.x, q10.y, qa_hi[kt][1], qa_lo[kt][1]);
        split_pack(q01.x, q01.y, qa_hi[kt][2], qa_lo[kt][2]);
        split_pack(q11.x, q11.y, qa_hi[kt][3], qa_lo[kt][3]);
    }

    float pv[8][4];
#pragma unroll
    for (int nd = 0; nd < 8; nd++)
#pragma unroll
        for (int j = 0; j < 4; j++) pv[nd][j] = 0.f;

    float m0 = -3.0e38f, m1 = -3.0e38f, l0 = 0.f, l1 = 0.f;

    const int frow = tid >> 2;          // fill: row 0..63
    const int fd0  = (tid & 3) * 16;    // fill: 16 d-values
    __nv_bfloat16* vhiB = (__nv_bfloat16*)sVhi;
    __nv_bfloat16* vloB = (__nv_bfloat16*)sVlo;

    for (int s0 = 0; s0 < Ssq; s0 += ASC) {
        __syncthreads();
        // ---- fill K (hi/lo, [s][d]) and V (hi/lo, transposed [d][s]) ----
        {
            const float4* krow = (const float4*)(kbase + (size_t)(s0 + frow) * Dd);
            const float4* vrow = (const float4*)(vbase + (size_t)(s0 + frow) * Dd);
#pragma unroll
            for (int i = 0; i < 4; i++) {
                int d = fd0 + 4 * i;
                float4 kv = krow[d >> 2];
                unsigned h0, h1, e0, e1;
                split_pack(kv.x, kv.y, h0, e0);
                split_pack(kv.z, kv.w, h1, e1);
                sKhi[frow * KW + (d >> 1)]     = h0;
                sKhi[frow * KW + (d >> 1) + 1] = h1;
                sKlo[frow * KW + (d >> 1)]     = e0;
                sKlo[frow * KW + (d >> 1) + 1] = e1;

                float4 vv = vrow[d >> 2];
                float ve[4] = {vv.x, vv.y, vv.z, vv.w};
#pragma unroll
                for (int e = 0; e < 4; e++) {
                    __nv_bfloat16 hb = __float2bfloat16_rn(ve[e]);
                    __nv_bfloat16 lb =
                        __float2bfloat16_rn(ve[e] - __bfloat162float(hb));
                    vhiB[(d + e) * (2 * KW) + frow] = hb;
                    vloB[(d + e) * (2 * KW) + frow] = lb;
                }
            }
        }
        __syncthreads();

        // ---- scores: S[16][64] per warp via split-3 bf16 MMA ----
        float sacc[8][4];
#pragma unroll
        for (int nt = 0; nt < 8; nt++) {
#pragma unroll
            for (int j = 0; j < 4; j++) sacc[nt][j] = 0.f;
            int nrow = nt * 8 + lq;
#pragma unroll
            for (int kt = 0; kt < 4; kt++) {
                unsigned bh0 = sKhi[nrow * KW + 8 * kt + lr];
                unsigned bh1 = sKhi[nrow * KW + 8 * kt + lr + 4];
                unsigned bl0 = sKlo[nrow * KW + 8 * kt + lr];
                unsigned bl1 = sKlo[nrow * KW + 8 * kt + lr + 4];
                mma_bf16(sacc[nt], qa_hi[kt][0], qa_hi[kt][1], qa_hi[kt][2],
                         qa_hi[kt][3], bh0, bh1);
                mma_bf16(sacc[nt], qa_hi[kt][0], qa_hi[kt][1], qa_hi[kt][2],
                         qa_hi[kt][3], bl0, bl1);
                mma_bf16(sacc[nt], qa_lo[kt][0], qa_lo[kt][1], qa_lo[kt][2],
                         qa_lo[kt][3], bh0, bh1);
            }
        }

        // ---- masks ----
#pragma unroll
        for (int nt = 0; nt < 8; nt++) {
            int sg = s0 + nt * 8 + 2 * lr;
            uchar2 km  = *(const uchar2*)(kpmb + sg);
            uchar2 am0 = *(const uchar2*)(amask + (size_t)rg0 * Ssq + sg);
            uchar2 am1 = *(const uchar2*)(amask + (size_t)rg1 * Ssq + sg);
            if (km.x | am0.x) sacc[nt][0] = -1e30f;
            if (km.y | am0.y) sacc[nt][1] = -1e30f;
            if (km.x | am1.x) sacc[nt][2] = -1e30f;
            if (km.y | am1.y) sacc[nt][3] = -1e30f;
        }

        // ---- raw score store (normalized later) ----
        if (attnw) {
            size_t base0 = ((size_t)(b * Hh + h) * Tt + rg0) * Ssq + s0 + 2 * lr;
            size_t base1 = ((size_t)(b * Hh + h) * Tt + rg1) * Ssq + s0 + 2 * lr;
#pragma unroll
            for (int nt = 0; nt < 8; nt++) {
                *(float2*)(attnw + base0 + nt * 8) =
                    make_float2(sacc[nt][0], sacc[nt][1]);
                *(float2*)(attnw + base1 + nt * 8) =
                    make_float2(sacc[nt][2], sacc[nt][3]);
            }
        }

        // ---- online softmax (warp-local rows) ----
        float mx0 = -3.0e38f, mx1 = -3.0e38f;
#pragma unroll
        for (int nt = 0; nt < 8; nt++) {
            mx0 = fmaxf(mx0, fmaxf(sacc[nt][0], sacc[nt][1]));
            mx1 = fmaxf(mx1, fmaxf(sacc[nt][2], sacc[nt][3]));
        }
        mx0 = fmaxf(mx0, __shfl_xor_sync(0xffffffffu, mx0, 1));
        mx0 = fmaxf(mx0, __shfl_xor_sync(0xffffffffu, mx0, 2));
        mx1 = fmaxf(mx1, __shfl_xor_sync(0xffffffffu, mx1, 1));
        mx1 = fmaxf(mx1, __shfl_xor_sync(0xffffffffu, mx1, 2));

        float mn0 = fmaxf(m0, mx0), mn1 = fmaxf(m1, mx1);
        float f0 = __expf(m0 - mn0), f1 = __expf(m1 - mn1);
        m0 = mn0; m1 = mn1;
#pragma unroll
        for (int nd = 0; nd < 8; nd++) {
            pv[nd][0] *= f0; pv[nd][1] *= f0;
            pv[nd][2] *= f1; pv[nd][3] *= f1;
        }

        // ---- p = exp(s-m): build P A-fragments (hi/lo) + row sums ----
        unsigned pa_hi[4][4], pa_lo[4][4];
        float rs0 = 0.f, rs1 = 0.f;
#pragma unroll
        for (int kt = 0; kt < 4; kt++) {
            float p00 = __expf(sacc[2 * kt][0] - m0);
            float p01 = __expf(sacc[2 * kt][1] - m0);
            float p02 = __expf(sacc[2 * kt][2] - m1);
            float p03 = __expf(sacc[2 * kt][3] - m1);
            float p10 = __expf(sacc[2 * kt + 1][0] - m0);
            float p11 = __expf(sacc[2 * kt + 1][1] - m0);
            float p12 = __expf(sacc[2 * kt + 1][2] - m1);
            float p13 = __expf(sacc[2 * kt + 1][3] - m1);
            rs0 += p00 + p01 + p10 + p11;
            rs1 += p02 + p03 + p12 + p13;
            split_pack(p00, p01, pa_hi[kt][0], pa_lo[kt][0]);
            split_pack(p02, p03, pa_hi[kt][1], pa_lo[kt][1]);
            split_pack(p10, p11, pa_hi[kt][2], pa_lo[kt][2]);
            split_pack(p12, p13, pa_hi[kt][3], pa_lo[kt][3]);
        }
        rs0 += __shfl_xor_sync(0xffffffffu, rs0, 1);
        rs0 += __shfl_xor_sync(0xffffffffu, rs0, 2);
        rs1 += __shfl_xor_sync(0xffffffffu, rs1, 1);
        rs1 += __shfl_xor_sync(0xffffffffu, rs1, 2);
        l0 = l0 * f0 + rs0;
        l1 = l1 * f1 + rs1;

        // ---- PV: pv += P @ V  (split-3) ----
#pragma unroll
        for (int nd = 0; nd < 8; nd++) {
            int nrow = nd * 8 + lq;   // d index (Vt row)
#pragma unroll
            for (int kt = 0; kt < 4; kt++) {
                unsigned bh0 = sVhi[nrow * KW + 8 * kt + lr];
                unsigned bh1 = sVhi[nrow * KW + 8 * kt + lr + 4];
                unsigned bl0 = sVlo[nrow * KW + 8 * kt + lr];
                unsigned bl1 = sVlo[nrow * KW + 8 * kt + lr + 4];
                mma_bf16(pv[nd], pa_hi[kt][0], pa_hi[kt][1], pa_hi[kt][2],
                         pa_hi[kt][3], bh0, bh1);
                mma_bf16(pv[nd], pa_hi[kt][0], pa_hi[kt][1], pa_hi[kt][2],
                         pa_hi[kt][3], bl0, bl1);
                mma_bf16(pv[nd], pa_lo[kt][0], pa_lo[kt][1], pa_lo[kt][2],
                         pa_lo[kt][3], bh0, bh1);
            }
        }
    }

    // ---- epilogue: normalize rows, write [B,T,E] ----
    float inv0 = 1.f / l0, inv1 = 1.f / l1;
    int bcol = h * Dd + 2 * lr;
    size_t ob0 = ((size_t)b * Tt + rg0) * Ee + bcol;
    size_t ob1 = ((size_t)b * Tt + rg1) * Ee + bcol;
#pragma unroll
    for (int nd = 0; nd < 8; nd++) {
        *(float2*)(g_attnout + ob0 + nd * 8) =
            make_float2(pv[nd][0] * inv0, pv[nd][1] * inv0);
        *(float2*)(g_attnout + ob1 + nd * 8) =
            make_float2(pv[nd][2] * inv1, pv[nd][3] * inv1);
    }
    if (lr == 0) {
        size_t rowbase = (size_t)(b * Hh + h) * Tt + t0 + 16 * w;
        g_rowm[rowbase + lq]     = m0;
        g_rowm[rowbase + lq + 8] = m1;
        g_rowl[rowbase + lq]     = l0;
        g_rowl[rowbase + lq + 8] = l1;
    }
}

// ---------------- normalize raw scores -> softmax weights, in place ----------------
__global__ void normalize_attn(float* __restrict__ attnw)
{
    const size_t n4 = (size_t)Bb * Hh * Tt * Ssq / 4;
    float4* a4 = (float4*)attnw;
    for (size_t i = (size_t)blockIdx.x * blockDim.x + threadIdx.x; i < n4;
         i += (size_t)gridDim.x * blockDim.x) {
        size_t row = (i * 4) / Ssq;
        float m = g_rowm[row];
        float invl = 1.f / g_rowl[row];
        float4 v = a4[i];
        v.x = __expf(v.x - m) * invl;
        v.y = __expf(v.y - m) * invl;
        v.z = __expf(v.z - m) * invl;
        v.w = __expf(v.w - m) * invl;
        a4[i] = v;
    }
}

// ---------------- launch ----------------
extern "C" void kernel_launch(void* const* d_in, const int* in_sizes, int n_in,
                              void* d_out, int out_size)
{
    const float* query = (const float*)d_in[0];
    const float* key   = (const float*)d_in[1];
    const float* value = (const float*)d_in[2];
    const unsigned char* kpm = (const unsigned char*)d_in[3];
    const unsigned char* am  = (const unsigned char*)d_in[4];
    const float* Wq = (const float*)d_in[5];  const float* bq = (const float*)d_in[6];
    const float* Wk = (const float*)d_in[7];  const float* bk = (const float*)d_in[8];
    const float* Wv = (const float*)d_in[9];  const float* bv = (const float*)d_in[10];
    const float* Wo = (const float*)d_in[11]; const float* bo = (const float*)d_in[12];

    float *qp, *kp, *vp, *aop;
    cudaGetSymbolAddress((void**)&qp,  g_q);
    cudaGetSymbolAddress((void**)&kp,  g_k);
    cudaGetSymbolAddress((void**)&vp,  g_v);
    cudaGetSymbolAddress((void**)&aop, g_attnout);

    const long long OUT_E  = (long long)Bb * Tt * Ee;                  // 4,194,304
    const long long ATTN_E = (long long)Bb * Hh * Tt * (long long)Ssq; // 134,217,728
    float* out_main = nullptr;
    float* out_attn = nullptr;
    if ((long long)out_size >= OUT_E + ATTN_E) {
        out_main = (float*)d_out;
        out_attn = (float*)d_out + OUT_E;
    } else if ((long long)out_size == ATTN_E) {
        out_attn = (float*)d_out;
    } else {
        out_main = (float*)d_out;
    }

    dim3 pg(Ee / BN, BT / BM);  // (4, 64)

    // projections (head-split layout; Q pre-scaled by Dh^-0.5)
    sgemm_bias<<<pg, 256>>>(query, Wq, bq, qp, 0.125f, 1);
    sgemm_bias<<<pg, 256>>>(key,   Wk, bk, kp, 1.0f,   1);
    sgemm_bias<<<pg, 256>>>(value, Wv, bv, vp, 1.0f,   1);

    // tensor-core fused attention
    dim3 ag(Tt / AQT, Hh, Bb);  // (16, 8, 4)
    attn_kernel<<<ag, 256>>>(kpm, am, out_attn);

    if (out_attn) normalize_attn<<<2048, 256>>>(out_attn);

    if (out_main) sgemm_bias<<<pg, 256>>>(aop, Wo, bo, out_main, 1.0f, 0);
}

// round 12
// speedup vs baseline: 1.4625x; 1.0325x over previous
#include <cuda_runtime.h>
#include <cuda_bf16.h>

// ---------------- problem constants ----------------
constexpr int Bb = 4, Tt = 2048, Ssq = 2048, Ee = 512, Hh = 8, Dd = 64;
constexpr int BT = Bb * Tt;

// ---------------- device scratch (no cudaMalloc allowed) ----------------
__device__ float g_q[(size_t)Bb * Hh * Tt * Dd];       // [B,H,T,64], pre-scaled
__device__ float g_k[(size_t)Bb * Hh * Ssq * Dd];      // [B,H,S,64]
__device__ float g_v[(size_t)Bb * Hh * Ssq * Dd];      // [B,H,S,64]
__device__ float g_attnout[(size_t)BT * Ee];           // [B,T,E] pre-output-proj
__device__ float g_rowm[(size_t)Bb * Hh * Tt];         // per-row softmax max
__device__ float g_rowl[(size_t)Bb * Hh * Tt];         // per-row softmax denom

// ---------------- SGEMM: C = A[M,K] @ W[K,N] + bias, optional head layout ----------------
constexpr int BM = 128, BN = 128, BKk = 8, TM = 8, TN = 8;

__global__ __launch_bounds__(256, 2) void sgemm_bias(
    const float* __restrict__ A, const float* __restrict__ W,
    const float* __restrict__ bias, float* __restrict__ C,
    float scale, int head_layout)
{
    __shared__ float As[BKk][BM];
    __shared__ float Ws[BKk][BN];
    const int K = Ee, N = Ee;
    const int tid  = threadIdx.x;
    const int tcol = tid & 15;
    const int trow = tid >> 4;
    const int aRow = tid >> 1;
    const int aCol = (tid & 1) * 4;
    const int wRow = tid >> 5;
    const int wCol = (tid & 31) * 4;

    const float* Ab = A + (size_t)blockIdx.y * BM * K;
    const float* Wb = W + blockIdx.x * BN;

    float acc[TM][TN];
#pragma unroll
    for (int i = 0; i < TM; i++)
#pragma unroll
        for (int j = 0; j < TN; j++) acc[i][j] = 0.f;

    for (int k0 = 0; k0 < K; k0 += BKk) {
        float4 av = *(const float4*)(Ab + (size_t)aRow * K + k0 + aCol);
        As[aCol + 0][aRow] = av.x;
        As[aCol + 1][aRow] = av.y;
        As[aCol + 2][aRow] = av.z;
        As[aCol + 3][aRow] = av.w;
        *(float4*)(&Ws[wRow][wCol]) = *(const float4*)(Wb + (size_t)(k0 + wRow) * N + wCol);
        __syncthreads();
#pragma unroll
        for (int k = 0; k < BKk; k++) {
            float4 a0 = *(const float4*)&As[k][trow * TM];
            float4 a1 = *(const float4*)&As[k][trow * TM + 4];
            float4 b0 = *(const float4*)&Ws[k][tcol * TN];
            float4 b1 = *(const float4*)&Ws[k][tcol * TN + 4];
            float ar[8] = {a0.x, a0.y, a0.z, a0.w, a1.x, a1.y, a1.z, a1.w};
            float br[8] = {b0.x, b0.y, b0.z, b0.w, b1.x, b1.y, b1.z, b1.w};
#pragma unroll
            for (int i = 0; i < TM; i++)
#pragma unroll
                for (int j = 0; j < TN; j++) acc[i][j] = fmaf(ar[i], br[j], acc[i][j]);
        }
        __syncthreads();
    }

#pragma unroll
    for (int i = 0; i < TM; i++) {
        int m = blockIdx.y * BM + trow * TM + i;
        int b = m / Tt, t = m % Tt;
#pragma unroll
        for (int j = 0; j < TN; j++) {
            int n = blockIdx.x * BN + tcol * TN + j;
            float v = (acc[i][j] + bias[n]) * scale;
            if (head_layout) {
                int h = n >> 6, d = n & 63;
                C[((size_t)(b * Hh + h) * Tt + t) * Dd + d] = v;
            } else {
                C[(size_t)m * N + n] = v;
            }
        }
    }
}

// ================= tensor-core fused attention =================
// CTA = 128 q rows (8 warps x m16), S chunks of 64.
// QK^T and PV on mma.sync.m16n8k16 bf16, 2-term split (hi+lo):
//   a*b ~= ah*bh + ah*bl + al*bh
// B-fragments fed via ldmatrix (x4 for K, x4.trans for natural-layout V).
// smem rows: 72 bf16 = 144B stride -> 16B aligned, conflict-free LDSM.

constexpr int AQT = 128;   // q rows per CTA
constexpr int ASC = 64;    // s chunk
constexpr int KW  = 36;    // u32 words per smem row (72 bf16)
constexpr int ROWB = 144;  // row stride in bytes

__device__ __forceinline__ void mma_bf16(float c[4], const unsigned a[4],
                                         unsigned b0, unsigned b1)
{
    asm volatile(
        "mma.sync.aligned.m16n8k16.row.col.f32.bf16.bf16.f32 "
        "{%0,%1,%2,%3}, {%4,%5,%6,%7}, {%8,%9}, {%0,%1,%2,%3};"
        : "+f"(c[0]), "+f"(c[1]), "+f"(c[2]), "+f"(c[3])
        : "r"(a[0]), "r"(a[1]), "r"(a[2]), "r"(a[3]), "r"(b0), "r"(b1));
}

__device__ __forceinline__ void ldsm_x4(unsigned& r0, unsigned& r1,
                                        unsigned& r2, unsigned& r3, unsigned addr)
{
    asm volatile("ldmatrix.sync.aligned.m8n8.x4.shared.b16 {%0,%1,%2,%3}, [%4];"
                 : "=r"(r0), "=r"(r1), "=r"(r2), "=r"(r3) : "r"(addr));
}

__device__ __forceinline__ void ldsm_x4_t(unsigned& r0, unsigned& r1,
                                          unsigned& r2, unsigned& r3, unsigned addr)
{
    asm volatile("ldmatrix.sync.aligned.m8n8.x4.trans.shared.b16 {%0,%1,%2,%3}, [%4];"
                 : "=r"(r0), "=r"(r1), "=r"(r2), "=r"(r3) : "r"(addr));
}

__device__ __forceinline__ void split_pack(float x, float y,
                                           unsigned& hi, unsigned& lo)
{
    __nv_bfloat162 h = __floats2bfloat162_rn(x, y);
    float hx = __bfloat162float(__low2bfloat16(h));
    float hy = __bfloat162float(__high2bfloat16(h));
    __nv_bfloat162 l2 = __floats2bfloat162_rn(x - hx, y - hy);
    hi = *reinterpret_cast<unsigned*>(&h);
    lo = *reinterpret_cast<unsigned*>(&l2);
}

__global__ __launch_bounds__(256, 1) void attn_kernel(
    const unsigned char* __restrict__ kpm,    // [B,S] bool
    const unsigned char* __restrict__ amask,  // [T,S] bool
    float* __restrict__ attnw)                // raw-score scratch (may be null)
{
    __shared__ unsigned sKhi[ASC * KW];   // K hi, [s][d] natural
    __shared__ unsigned sKlo[ASC * KW];
    __shared__ unsigned sVhi[ASC * KW];   // V hi, [s][d] natural
    __shared__ unsigned sVlo[ASC * KW];

    const int b  = blockIdx.z, h = blockIdx.y;
    const int t0 = blockIdx.x * AQT;
    const int tid = threadIdx.x;
    const int w   = tid >> 5;
    const int l   = tid & 31;
    const int lq  = l >> 2;     // groupID
    const int lr  = l & 3;

    const unsigned kHiA = (unsigned)__cvta_generic_to_shared(sKhi);
    const unsigned kLoA = (unsigned)__cvta_generic_to_shared(sKlo);
    const unsigned vHiA = (unsigned)__cvta_generic_to_shared(sVhi);
    const unsigned vLoA = (unsigned)__cvta_generic_to_shared(sVlo);

    // per-lane static LDSM offsets
    const int lm8 = l & 7;
    const unsigned sc_off = (unsigned)(((l >> 4) * 8 + lm8) * ROWB + ((l >> 3) & 1) * 16);
    const unsigned pv_off = (unsigned)((((l >> 3) & 1) * 8 + lm8) * ROWB + (l >> 4) * 16);

    const float* qbase = g_q + (size_t)(b * Hh + h) * Tt * Dd;
    const float* kbase = g_k + (size_t)(b * Hh + h) * Ssq * Dd;
    const float* vbase = g_v + (size_t)(b * Hh + h) * Ssq * Dd;
    const unsigned char* kpmb = kpm + (size_t)b * Ssq;

    const int rg0 = t0 + 16 * w + lq;
    const int rg1 = rg0 + 8;

    // ---- Q A-fragments (hi/lo), loaded once ----
    unsigned qa_hi[4][4], qa_lo[4][4];
#pragma unroll
    for (int kt = 0; kt < 4; kt++) {
        int c = 16 * kt + 2 * lr;
        float2 q00 = *(const float2*)(qbase + (size_t)rg0 * Dd + c);
        float2 q10 = *(const float2*)(qbase + (size_t)rg1 * Dd + c);
        float2 q01 = *(const float2*)(qbase + (size_t)rg0 * Dd + c + 8);
        float2 q11 = *(const float2*)(qbase + (size_t)rg1 * Dd + c + 8);
        split_pack(q00.x, q00.y, qa_hi[kt][0], qa_lo[kt][0]);
        split_pack(q10.x, q10.y, qa_hi[kt][1], qa_lo[kt][1]);
        split_pack(q01.x, q01.y, qa_hi[kt][2], qa_lo[kt][2]);
        split_pack(q11.x, q11.y, qa_hi[kt][3], qa_lo[kt][3]);
    }

    float pv[8][4];
#pragma unroll
    for (int nd = 0; nd < 8; nd++)
#pragma unroll
        for (int j = 0; j < 4; j++) pv[nd][j] = 0.f;

    float m0 = -3.0e38f, m1 = -3.0e38f, l0 = 0.f, l1 = 0.f;

    const int frow = tid >> 2;          // fill: row 0..63
    const int fd0  = (tid & 3) * 16;    // fill: 16 d-values

    for (int s0 = 0; s0 < Ssq; s0 += ASC) {
        __syncthreads();
        // ---- fill K and V (hi/lo, natural [s][d]) ----
        {
            const float4* krow = (const float4*)(kbase + (size_t)(s0 + frow) * Dd);
            const float4* vrow = (const float4*)(vbase + (size_t)(s0 + frow) * Dd);
#pragma unroll
            for (int i = 0; i < 4; i++) {
                int d = fd0 + 4 * i;
                float4 kv = krow[d >> 2];
                unsigned h0, h1, e0, e1;
                split_pack(kv.x, kv.y, h0, e0);
                split_pack(kv.z, kv.w, h1, e1);
                sKhi[frow * KW + (d >> 1)]     = h0;
                sKhi[frow * KW + (d >> 1) + 1] = h1;
                sKlo[frow * KW + (d >> 1)]     = e0;
                sKlo[frow * KW + (d >> 1) + 1] = e1;

                float4 vv = vrow[d >> 2];
                split_pack(vv.x, vv.y, h0, e0);
                split_pack(vv.z, vv.w, h1, e1);
                sVhi[frow * KW + (d >> 1)]     = h0;
                sVhi[frow * KW + (d >> 1) + 1] = h1;
                sVlo[frow * KW + (d >> 1)]     = e0;
                sVlo[frow * KW + (d >> 1) + 1] = e1;
            }
        }
        __syncthreads();

        // ---- scores: S[16][64] per warp, LDSM-fed split MMA ----
        float sacc[8][4];
#pragma unroll
        for (int nt = 0; nt < 8; nt++)
#pragma unroll
            for (int j = 0; j < 4; j++) sacc[nt][j] = 0.f;

#pragma unroll
        for (int ntp = 0; ntp < 4; ntp++) {
            const int nt = ntp * 2;
            const unsigned base = nt * 8 * ROWB + sc_off;
#pragma unroll
            for (int kt = 0; kt < 4; kt++) {
                unsigned bh0, bh1, bh2, bh3, bl0, bl1, bl2, bl3;
                ldsm_x4(bh0, bh1, bh2, bh3, kHiA + base + kt * 32);
                ldsm_x4(bl0, bl1, bl2, bl3, kLoA + base + kt * 32);
                mma_bf16(sacc[nt],     qa_hi[kt], bh0, bh1);
                mma_bf16(sacc[nt],     qa_hi[kt], bl0, bl1);
                mma_bf16(sacc[nt],     qa_lo[kt], bh0, bh1);
                mma_bf16(sacc[nt + 1], qa_hi[kt], bh2, bh3);
                mma_bf16(sacc[nt + 1], qa_hi[kt], bl2, bl3);
                mma_bf16(sacc[nt + 1], qa_lo[kt], bh2, bh3);
            }
        }

        // ---- masks ----
#pragma unroll
        for (int nt = 0; nt < 8; nt++) {
            int sg = s0 + nt * 8 + 2 * lr;
            uchar2 km  = *(const uchar2*)(kpmb + sg);
            uchar2 am0 = *(const uchar2*)(amask + (size_t)rg0 * Ssq + sg);
            uchar2 am1 = *(const uchar2*)(amask + (size_t)rg1 * Ssq + sg);
            if (km.x | am0.x) sacc[nt][0] = -1e30f;
            if (km.y | am0.y) sacc[nt][1] = -1e30f;
            if (km.x | am1.x) sacc[nt][2] = -1e30f;
            if (km.y | am1.y) sacc[nt][3] = -1e30f;
        }

        // ---- raw score store (normalized later) ----
        if (attnw) {
            size_t base0 = ((size_t)(b * Hh + h) * Tt + rg0) * Ssq + s0 + 2 * lr;
            size_t base1 = ((size_t)(b * Hh + h) * Tt + rg1) * Ssq + s0 + 2 * lr;
#pragma unroll
            for (int nt = 0; nt < 8; nt++) {
                *(float2*)(attnw + base0 + nt * 8) =
                    make_float2(sacc[nt][0], sacc[nt][1]);
                *(float2*)(attnw + base1 + nt * 8) =
                    make_float2(sacc[nt][2], sacc[nt][3]);
            }
        }

        // ---- online softmax (warp-local rows) ----
        float mx0 = -3.0e38f, mx1 = -3.0e38f;
#pragma unroll
        for (int nt = 0; nt < 8; nt++) {
            mx0 = fmaxf(mx0, fmaxf(sacc[nt][0], sacc[nt][1]));
            mx1 = fmaxf(mx1, fmaxf(sacc[nt][2], sacc[nt][3]));
        }
        mx0 = fmaxf(mx0, __shfl_xor_sync(0xffffffffu, mx0, 1));
        mx0 = fmaxf(mx0, __shfl_xor_sync(0xffffffffu, mx0, 2));
        mx1 = fmaxf(mx1, __shfl_xor_sync(0xffffffffu, mx1, 1));
        mx1 = fmaxf(mx1, __shfl_xor_sync(0xffffffffu, mx1, 2));

        float mn0 = fmaxf(m0, mx0), mn1 = fmaxf(m1, mx1);
        float f0 = __expf(m0 - mn0), f1 = __expf(m1 - mn1);
        m0 = mn0; m1 = mn1;
#pragma unroll
        for (int nd = 0; nd < 8; nd++) {
            pv[nd][0] *= f0; pv[nd][1] *= f0;
            pv[nd][2] *= f1; pv[nd][3] *= f1;
        }

        // ---- p = exp(s-m): build P A-fragments (hi/lo) + row sums ----
        unsigned pa_hi[4][4], pa_lo[4][4];
        float rs0 = 0.f, rs1 = 0.f;
#pragma unroll
        for (int kt = 0; kt < 4; kt++) {
            float p00 = __expf(sacc[2 * kt][0] - m0);
            float p01 = __expf(sacc[2 * kt][1] - m0);
            float p02 = __expf(sacc[2 * kt][2] - m1);
            float p03 = __expf(sacc[2 * kt][3] - m1);
            float p10 = __expf(sacc[2 * kt + 1][0] - m0);
            float p11 = __expf(sacc[2 * kt + 1][1] - m0);
            float p12 = __expf(sacc[2 * kt + 1][2] - m1);
            float p13 = __expf(sacc[2 * kt + 1][3] - m1);
            rs0 += p00 + p01 + p10 + p11;
            rs1 += p02 + p03 + p12 + p13;
            split_pack(p00, p01, pa_hi[kt][0], pa_lo[kt][0]);
            split_pack(p02, p03, pa_hi[kt][1], pa_lo[kt][1]);
            split_pack(p10, p11, pa_hi[kt][2], pa_lo[kt][2]);
            split_pack(p12, p13, pa_hi[kt][3], pa_lo[kt][3]);
        }
        rs0 += __shfl_xor_sync(0xffffffffu, rs0, 1);
        rs0 += __shfl_xor_sync(0xffffffffu, rs0, 2);
        rs1 += __shfl_xor_sync(0xffffffffu, rs1, 1);
        rs1 += __shfl_xor_sync(0xffffffffu, rs1, 2);
        l0 = l0 * f0 + rs0;
        l1 = l1 * f1 + rs1;

        // ---- PV: pv += P @ V  (V natural layout, trans-LDSM B-frags) ----
#pragma unroll
        for (int ndp = 0; ndp < 4; ndp++) {
            const int nd = ndp * 2;
            const unsigned vb = nd * 16 + pv_off;
#pragma unroll
            for (int kt = 0; kt < 4; kt++) {
                unsigned bh0, bh1, bh2, bh3, bl0, bl1, bl2, bl3;
                ldsm_x4_t(bh0, bh1, bh2, bh3, vHiA + kt * (16 * ROWB) + vb);
                ldsm_x4_t(bl0, bl1, bl2, bl3, vLoA + kt * (16 * ROWB) + vb);
                mma_bf16(pv[nd],     pa_hi[kt], bh0, bh1);
                mma_bf16(pv[nd],     pa_hi[kt], bl0, bl1);
                mma_bf16(pv[nd],     pa_lo[kt], bh0, bh1);
                mma_bf16(pv[nd + 1], pa_hi[kt], bh2, bh3);
                mma_bf16(pv[nd + 1], pa_hi[kt], bl2, bl3);
                mma_bf16(pv[nd + 1], pa_lo[kt], bh2, bh3);
            }
        }
    }

    // ---- epilogue: normalize rows, write [B,T,E] ----
    float inv0 = 1.f / l0, inv1 = 1.f / l1;
    int bcol = h * Dd + 2 * lr;
    size_t ob0 = ((size_t)b * Tt + rg0) * Ee + bcol;
    size_t ob1 = ((size_t)b * Tt + rg1) * Ee + bcol;
#pragma unroll
    for (int nd = 0; nd < 8; nd++) {
        *(float2*)(g_attnout + ob0 + nd * 8) =
            make_float2(pv[nd][0] * inv0, pv[nd][1] * inv0);
        *(float2*)(g_attnout + ob1 + nd * 8) =
            make_float2(pv[nd][2] * inv1, pv[nd][3] * inv1);
    }
    if (lr == 0) {
        size_t rowbase = (size_t)(b * Hh + h) * Tt + t0 + 16 * w;
        g_rowm[rowbase + lq]     = m0;
        g_rowm[rowbase + lq + 8] = m1;
        g_rowl[rowbase + lq]     = l0;
        g_rowl[rowbase + lq + 8] = l1;
    }
}

// ---------------- normalize raw scores -> softmax weights, in place ----------------
__global__ void normalize_attn(float* __restrict__ attnw)
{
    const size_t n4 = (size_t)Bb * Hh * Tt * Ssq / 4;
    float4* a4 = (float4*)attnw;
    for (size_t i = (size_t)blockIdx.x * blockDim.x + threadIdx.x; i < n4;
         i += (size_t)gridDim.x * blockDim.x) {
        size_t row = (i * 4) / Ssq;
        float m = g_rowm[row];
        float invl = 1.f / g_rowl[row];
        float4 v = a4[i];
        v.x = __expf(v.x - m) * invl;
        v.y = __expf(v.y - m) * invl;
        v.z = __expf(v.z - m) * invl;
        v.w = __expf(v.w - m) * invl;
        a4[i] = v;
    }
}

// ---------------- launch ----------------
extern "C" void kernel_launch(void* const* d_in, const int* in_sizes, int n_in,
                              void* d_out, int out_size)
{
    const float* query = (const float*)d_in[0];
    const float* key   = (const float*)d_in[1];
    const float* value = (const float*)d_in[2];
    const unsigned char* kpm = (const unsigned char*)d_in[3];
    const unsigned char* am  = (const unsigned char*)d_in[4];
    const float* Wq = (const float*)d_in[5];  const float* bq = (const float*)d_in[6];
    const float* Wk = (const float*)d_in[7];  const float* bk = (const float*)d_in[8];
    const float* Wv = (const float*)d_in[9];  const float* bv = (const float*)d_in[10];
    const float* Wo = (const float*)d_in[11]; const float* bo = (const float*)d_in[12];

    float *qp, *kp, *vp, *aop;
    cudaGetSymbolAddress((void**)&qp,  g_q);
    cudaGetSymbolAddress((void**)&kp,  g_k);
    cudaGetSymbolAddress((void**)&vp,  g_v);
    cudaGetSymbolAddress((void**)&aop, g_attnout);

    const long long OUT_E  = (long long)Bb * Tt * Ee;                  // 4,194,304
    const long long ATTN_E = (long long)Bb * Hh * Tt * (long long)Ssq; // 134,217,728
    float* out_main = nullptr;
    float* out_attn = nullptr;
    if ((long long)out_size >= OUT_E + ATTN_E) {
        out_main = (float*)d_out;
        out_attn = (float*)d_out + OUT_E;
    } else if ((long long)out_size == ATTN_E) {
        out_attn = (float*)d_out;
    } else {
        out_main = (float*)d_out;
    }

    dim3 pg(Ee / BN, BT / BM);  // (4, 64)

    // projections (head-split layout; Q pre-scaled by Dh^-0.5)
    sgemm_bias<<<pg, 256>>>(query, Wq, bq, qp, 0.125f, 1);
    sgemm_bias<<<pg, 256>>>(key,   Wk, bk, kp, 1.0f,   1);
    sgemm_bias<<<pg, 256>>>(value, Wv, bv, vp, 1.0f,   1);

    // tensor-core fused attention (LDSM-fed)
    dim3 ag(Tt / AQT, Hh, Bb);  // (16, 8, 4)
    attn_kernel<<<ag, 256>>>(kpm, am, out_attn);

    if (out_attn) normalize_attn<<<2048, 256>>>(out_attn);

    if (out_main) sgemm_bias<<<pg, 256>>>(aop, Wo, bo, out_main, 1.0f, 0);
}

// round 13
// speedup vs baseline: 1.9195x; 1.3124x over previous
#include <cuda_runtime.h>
#include <cuda_bf16.h>

// ---------------- problem constants ----------------
constexpr int Bb = 4, Tt = 2048, Ssq = 2048, Ee = 512, Hh = 8, Dd = 64;
constexpr int BT = Bb * Tt;

// ---------------- device scratch (no cudaMalloc allowed) ----------------
__device__ float g_q[(size_t)Bb * Hh * Tt * Dd];       // [B,H,T,64], pre-scaled
__device__ float g_k[(size_t)Bb * Hh * Ssq * Dd];      // [B,H,S,64]
__device__ float g_v[(size_t)Bb * Hh * Ssq * Dd];      // [B,H,S,64]
__device__ float g_attnout[(size_t)BT * Ee];           // [B,T,E] pre-output-proj
__device__ float g_rowm[(size_t)Bb * Hh * Tt];         // per-row softmax max
__device__ float g_rowl[(size_t)Bb * Hh * Tt];         // per-row softmax denom
// bf16 hi/lo split buffers (reused sequentially per GEMM)
__device__ unsigned g_ahi[(size_t)BT * Ee / 2];        // A hi: [M][K/2] u32
__device__ unsigned g_alo[(size_t)BT * Ee / 2];
__device__ unsigned g_whi[(size_t)Ee * Ee / 2];        // W hi: [K][N/2] u32
__device__ unsigned g_wlo[(size_t)Ee * Ee / 2];

// ---------------- common helpers ----------------
__device__ __forceinline__ void mma_bf16(float c[4], const unsigned a[4],
                                         unsigned b0, unsigned b1)
{
    asm volatile(
        "mma.sync.aligned.m16n8k16.row.col.f32.bf16.bf16.f32 "
        "{%0,%1,%2,%3}, {%4,%5,%6,%7}, {%8,%9}, {%0,%1,%2,%3};"
        : "+f"(c[0]), "+f"(c[1]), "+f"(c[2]), "+f"(c[3])
        : "r"(a[0]), "r"(a[1]), "r"(a[2]), "r"(a[3]), "r"(b0), "r"(b1));
}

__device__ __forceinline__ void ldsm_x4(unsigned& r0, unsigned& r1,
                                        unsigned& r2, unsigned& r3, unsigned addr)
{
    asm volatile("ldmatrix.sync.aligned.m8n8.x4.shared.b16 {%0,%1,%2,%3}, [%4];"
                 : "=r"(r0), "=r"(r1), "=r"(r2), "=r"(r3) : "r"(addr));
}

__device__ __forceinline__ void ldsm_x4_t(unsigned& r0, unsigned& r1,
                                          unsigned& r2, unsigned& r3, unsigned addr)
{
    asm volatile("ldmatrix.sync.aligned.m8n8.x4.trans.shared.b16 {%0,%1,%2,%3}, [%4];"
                 : "=r"(r0), "=r"(r1), "=r"(r2), "=r"(r3) : "r"(addr));
}

__device__ __forceinline__ void split_pack(float x, float y,
                                           unsigned& hi, unsigned& lo)
{
    __nv_bfloat162 h = __floats2bfloat162_rn(x, y);
    float hx = __bfloat162float(__low2bfloat16(h));
    float hy = __bfloat162float(__high2bfloat16(h));
    __nv_bfloat162 l2 = __floats2bfloat162_rn(x - hx, y - hy);
    hi = *reinterpret_cast<unsigned*>(&h);
    lo = *reinterpret_cast<unsigned*>(&l2);
}

// ---------------- elementwise fp32 -> bf16 hi/lo split ----------------
__global__ void split_bf16(const float* __restrict__ in,
                           unsigned* __restrict__ hi, unsigned* __restrict__ lo,
                           int n2)
{
    const float2* in2 = (const float2*)in;
    for (int i = blockIdx.x * blockDim.x + threadIdx.x; i < n2;
         i += gridDim.x * blockDim.x) {
        float2 v = in2[i];
        unsigned h, l;
        split_pack(v.x, v.y, h, l);
        hi[i] = h;
        lo[i] = l;
    }
}

// ---------------- tensor-core GEMM: C = A[M,512] @ W[512,512] + bias ----------------
// split-3 bf16: ah*bh + ah*bl + al*bh. CTA tile 128x128, 8 warps (2m x 4n),
// warp tile 64x32, k-chunk 32. A smem rows 80B, W smem rows 272B (conflict-free).
constexpr int GK = 512, GN = 512;
constexpr int GROWA_U = 20;   // u32 per A smem row (40 bf16 = 80B)
constexpr int GROWW_U = 68;   // u32 per W smem row (136 bf16 = 272B)

__global__ __launch_bounds__(256, 2) void gemm_bf16_split(
    const unsigned* __restrict__ Ahi, const unsigned* __restrict__ Alo,
    const unsigned* __restrict__ Whi, const unsigned* __restrict__ Wlo,
    const float* __restrict__ bias, float* __restrict__ C,
    float scale, int head_layout)
{
    __shared__ unsigned sAhi[128 * GROWA_U];
    __shared__ unsigned sAlo[128 * GROWA_U];
    __shared__ unsigned sWhi[32 * GROWW_U];
    __shared__ unsigned sWlo[32 * GROWW_U];

    const int tid = threadIdx.x;
    const int w = tid >> 5, l = tid & 31;
    const int lq = l >> 2, lr = l & 3;
    const int wm = w >> 2, wn = w & 3;

    const int m0 = blockIdx.y * 128;
    const int n0 = blockIdx.x * 128;

    float c[4][4][4];
#pragma unroll
    for (int mt = 0; mt < 4; mt++)
#pragma unroll
        for (int nt = 0; nt < 4; nt++)
#pragma unroll
            for (int j = 0; j < 4; j++) c[mt][nt][j] = 0.f;

    // fill indices
    const int arow = tid >> 1;            // 0..127
    const int acol = (tid & 1) * 8;       // u32 col
    const int wrow = tid >> 3;            // 0..31
    const int wcol = (tid & 7) * 8;       // u32 col

    const unsigned sAhiB = (unsigned)__cvta_generic_to_shared(sAhi);
    const unsigned sAloB = (unsigned)__cvta_generic_to_shared(sAlo);
    const unsigned sWhiB = (unsigned)__cvta_generic_to_shared(sWhi);
    const unsigned sWloB = (unsigned)__cvta_generic_to_shared(sWlo);

    // lane ldsm offsets (bytes)
    const unsigned aOff = (unsigned)((l & 15) * 80 + (l >> 4) * 16);
    const unsigned wOff = (unsigned)((((l >> 3) & 1) * 8 + (l & 7)) * 272 + (l >> 4) * 16);

    const size_t aRowBase = (size_t)(m0 + arow) * (GK / 2);

    for (int k0 = 0; k0 < GK; k0 += 32) {
        __syncthreads();
        {
            const uint4* ga = (const uint4*)(Ahi + aRowBase + k0 / 2 + acol);
            const uint4* gb = (const uint4*)(Alo + aRowBase + k0 / 2 + acol);
            *(uint4*)&sAhi[arow * GROWA_U + acol]     = ga[0];
            *(uint4*)&sAhi[arow * GROWA_U + acol + 4] = ga[1];
            *(uint4*)&sAlo[arow * GROWA_U + acol]     = gb[0];
            *(uint4*)&sAlo[arow * GROWA_U + acol + 4] = gb[1];
            size_t wbase = (size_t)(k0 + wrow) * (GN / 2) + n0 / 2 + wcol;
            const uint4* gw = (const uint4*)(Whi + wbase);
            const uint4* gx = (const uint4*)(Wlo + wbase);
            *(uint4*)&sWhi[wrow * GROWW_U + wcol]     = gw[0];
            *(uint4*)&sWhi[wrow * GROWW_U + wcol + 4] = gw[1];
            *(uint4*)&sWlo[wrow * GROWW_U + wcol]     = gx[0];
            *(uint4*)&sWlo[wrow * GROWW_U + wcol + 4] = gx[1];
        }
        __syncthreads();

#pragma unroll
        for (int kt = 0; kt < 2; kt++) {
            // B-fragments for this warp's 32 n-columns (2 n-pairs of 16)
            unsigned bh[4][2], bl[4][2];
            {
                unsigned addr = sWhiB + kt * (16 * 272) + wn * 64 + wOff;
                unsigned addl = sWloB + kt * (16 * 272) + wn * 64 + wOff;
                ldsm_x4_t(bh[0][0], bh[0][1], bh[1][0], bh[1][1], addr);
                ldsm_x4_t(bh[2][0], bh[2][1], bh[3][0], bh[3][1], addr + 32);
                ldsm_x4_t(bl[0][0], bl[0][1], bl[1][0], bl[1][1], addl);
                ldsm_x4_t(bl[2][0], bl[2][1], bl[3][0], bl[3][1], addl + 32);
            }
#pragma unroll
            for (int mt = 0; mt < 4; mt++) {
                unsigned ah[4], al[4];
                unsigned abase = (unsigned)((wm * 64 + mt * 16) * 80 + kt * 32) + aOff;
                ldsm_x4(ah[0], ah[1], ah[2], ah[3], sAhiB + abase);
                ldsm_x4(al[0], al[1], al[2], al[3], sAloB + abase);
#pragma unroll
                for (int nt = 0; nt < 4; nt++) {
                    mma_bf16(c[mt][nt], ah, bh[nt][0], bh[nt][1]);
                    mma_bf16(c[mt][nt], ah, bl[nt][0], bl[nt][1]);
                    mma_bf16(c[mt][nt], al, bh[nt][0], bh[nt][1]);
                }
            }
        }
    }

    // epilogue
#pragma unroll
    for (int mt = 0; mt < 4; mt++) {
        int gm0 = m0 + wm * 64 + mt * 16 + lq;
        int gm1 = gm0 + 8;
#pragma unroll
        for (int nt = 0; nt < 4; nt++) {
            int gn = n0 + wn * 32 + nt * 8 + 2 * lr;
            float b0 = bias[gn], b1 = bias[gn + 1];
            float2 v0 = make_float2((c[mt][nt][0] + b0) * scale,
                                    (c[mt][nt][1] + b1) * scale);
            float2 v1 = make_float2((c[mt][nt][2] + b0) * scale,
                                    (c[mt][nt][3] + b1) * scale);
            if (head_layout) {
                int h = gn >> 6, d = gn & 63;
                int b0i = gm0 >> 11, t0i = gm0 & 2047;
                int b1i = gm1 >> 11, t1i = gm1 & 2047;
                *(float2*)&C[((size_t)(b0i * Hh + h) * Tt + t0i) * Dd + d] = v0;
                *(float2*)&C[((size_t)(b1i * Hh + h) * Tt + t1i) * Dd + d] = v1;
            } else {
                *(float2*)&C[(size_t)gm0 * GN + gn] = v0;
                *(float2*)&C[(size_t)gm1 * GN + gn] = v1;
            }
        }
    }
}

// ================= tensor-core fused attention (unchanged from R12) =================
constexpr int AQT = 128;   // q rows per CTA
constexpr int ASC = 64;    // s chunk
constexpr int KW  = 36;    // u32 words per smem row (72 bf16)
constexpr int ROWB = 144;  // row stride in bytes

__global__ __launch_bounds__(256, 1) void attn_kernel(
    const unsigned char* __restrict__ kpm,    // [B,S] bool
    const unsigned char* __restrict__ amask,  // [T,S] bool
    float* __restrict__ attnw)                // raw-score scratch (may be null)
{
    __shared__ unsigned sKhi[ASC * KW];
    __shared__ unsigned sKlo[ASC * KW];
    __shared__ unsigned sVhi[ASC * KW];
    __shared__ unsigned sVlo[ASC * KW];

    const int b  = blockIdx.z, h = blockIdx.y;
    const int t0 = blockIdx.x * AQT;
    const int tid = threadIdx.x;
    const int w   = tid >> 5;
    const int l   = tid & 31;
    const int lq  = l >> 2;
    const int lr  = l & 3;

    const unsigned kHiA = (unsigned)__cvta_generic_to_shared(sKhi);
    const unsigned kLoA = (unsigned)__cvta_generic_to_shared(sKlo);
    const unsigned vHiA = (unsigned)__cvta_generic_to_shared(sVhi);
    const unsigned vLoA = (unsigned)__cvta_generic_to_shared(sVlo);

    const int lm8 = l & 7;
    const unsigned sc_off = (unsigned)(((l >> 4) * 8 + lm8) * ROWB + ((l >> 3) & 1) * 16);
    const unsigned pv_off = (unsigned)((((l >> 3) & 1) * 8 + lm8) * ROWB + (l >> 4) * 16);

    const float* qbase = g_q + (size_t)(b * Hh + h) * Tt * Dd;
    const float* kbase = g_k + (size_t)(b * Hh + h) * Ssq * Dd;
    const float* vbase = g_v + (size_t)(b * Hh + h) * Ssq * Dd;
    const unsigned char* kpmb = kpm + (size_t)b * Ssq;

    const int rg0 = t0 + 16 * w + lq;
    const int rg1 = rg0 + 8;

    unsigned qa_hi[4][4], qa_lo[4][4];
#pragma unroll
    for (int kt = 0; kt < 4; kt++) {
        int cc = 16 * kt + 2 * lr;
        float2 q00 = *(const float2*)(qbase + (size_t)rg0 * Dd + cc);
        float2 q10 = *(const float2*)(qbase + (size_t)rg1 * Dd + cc);
        float2 q01 = *(const float2*)(qbase + (size_t)rg0 * Dd + cc + 8);
        float2 q11 = *(const float2*)(qbase + (size_t)rg1 * Dd + cc + 8);
        split_pack(q00.x, q00.y, qa_hi[kt][0], qa_lo[kt][0]);
        split_pack(q10.x, q10.y, qa_hi[kt][1], qa_lo[kt][1]);
        split_pack(q01.x, q01.y, qa_hi[kt][2], qa_lo[kt][2]);
        split_pack(q11.x, q11.y, qa_hi[kt][3], qa_lo[kt][3]);
    }

    float pv[8][4];
#pragma unroll
    for (int nd = 0; nd < 8; nd++)
#pragma unroll
        for (int j = 0; j < 4; j++) pv[nd][j] = 0.f;

    float m0 = -3.0e38f, m1 = -3.0e38f, l0 = 0.f, l1 = 0.f;

    const int frow = tid >> 2;
    const int fd0  = (tid & 3) * 16;

    for (int s0 = 0; s0 < Ssq; s0 += ASC) {
        __syncthreads();
        {
            const float4* krow = (const float4*)(kbase + (size_t)(s0 + frow) * Dd);
            const float4* vrow = (const float4*)(vbase + (size_t)(s0 + frow) * Dd);
#pragma unroll
            for (int i = 0; i < 4; i++) {
                int d = fd0 + 4 * i;
                float4 kv = krow[d >> 2];
                unsigned h0, h1, e0, e1;
                split_pack(kv.x, kv.y, h0, e0);
                split_pack(kv.z, kv.w, h1, e1);
                sKhi[frow * KW + (d >> 1)]     = h0;
                sKhi[frow * KW + (d >> 1) + 1] = h1;
                sKlo[frow * KW + (d >> 1)]     = e0;
                sKlo[frow * KW + (d >> 1) + 1] = e1;

                float4 vv = vrow[d >> 2];
                split_pack(vv.x, vv.y, h0, e0);
                split_pack(vv.z, vv.w, h1, e1);
                sVhi[frow * KW + (d >> 1)]     = h0;
                sVhi[frow * KW + (d >> 1) + 1] = h1;
                sVlo[frow * KW + (d >> 1)]     = e0;
                sVlo[frow * KW + (d >> 1) + 1] = e1;
            }
        }
        __syncthreads();

        float sacc[8][4];
#pragma unroll
        for (int nt = 0; nt < 8; nt++)
#pragma unroll
            for (int j = 0; j < 4; j++) sacc[nt][j] = 0.f;

#pragma unroll
        for (int ntp = 0; ntp < 4; ntp++) {
            const int nt = ntp * 2;
            const unsigned base = nt * 8 * ROWB + sc_off;
#pragma unroll
            for (int kt = 0; kt < 4; kt++) {
                unsigned bh0, bh1, bh2, bh3, bl0, bl1, bl2, bl3;
                ldsm_x4(bh0, bh1, bh2, bh3, kHiA + base + kt * 32);
                ldsm_x4(bl0, bl1, bl2, bl3, kLoA + base + kt * 32);
                mma_bf16(sacc[nt],     qa_hi[kt], bh0, bh1);
                mma_bf16(sacc[nt],     qa_hi[kt], bl0, bl1);
                mma_bf16(sacc[nt],     qa_lo[kt], bh0, bh1);
                mma_bf16(sacc[nt + 1], qa_hi[kt], bh2, bh3);
                mma_bf16(sacc[nt + 1], qa_hi[kt], bl2, bl3);
                mma_bf16(sacc[nt + 1], qa_lo[kt], bh2, bh3);
            }
        }

#pragma unroll
        for (int nt = 0; nt < 8; nt++) {
            int sg = s0 + nt * 8 + 2 * lr;
            uchar2 km  = *(const uchar2*)(kpmb + sg);
            uchar2 am0 = *(const uchar2*)(amask + (size_t)rg0 * Ssq + sg);
            uchar2 am1 = *(const uchar2*)(amask + (size_t)rg1 * Ssq + sg);
            if (km.x | am0.x) sacc[nt][0] = -1e30f;
            if (km.y | am0.y) sacc[nt][1] = -1e30f;
            if (km.x | am1.x) sacc[nt][2] = -1e30f;
            if (km.y | am1.y) sacc[nt][3] = -1e30f;
        }

        if (attnw) {
            size_t base0 = ((size_t)(b * Hh + h) * Tt + rg0) * Ssq + s0 + 2 * lr;
            size_t base1 = ((size_t)(b * Hh + h) * Tt + rg1) * Ssq + s0 + 2 * lr;
#pragma unroll
            for (int nt = 0; nt < 8; nt++) {
                *(float2*)(attnw + base0 + nt * 8) =
                    make_float2(sacc[nt][0], sacc[nt][1]);
                *(float2*)(attnw + base1 + nt * 8) =
                    make_float2(sacc[nt][2], sacc[nt][3]);
            }
        }

        float mx0 = -3.0e38f, mx1 = -3.0e38f;
#pragma unroll
        for (int nt = 0; nt < 8; nt++) {
            mx0 = fmaxf(mx0, fmaxf(sacc[nt][0], sacc[nt][1]));
            mx1 = fmaxf(mx1, fmaxf(sacc[nt][2], sacc[nt][3]));
        }
        mx0 = fmaxf(mx0, __shfl_xor_sync(0xffffffffu, mx0, 1));
        mx0 = fmaxf(mx0, __shfl_xor_sync(0xffffffffu, mx0, 2));
        mx1 = fmaxf(mx1, __shfl_xor_sync(0xffffffffu, mx1, 1));
        mx1 = fmaxf(mx1, __shfl_xor_sync(0xffffffffu, mx1, 2));

        float mn0 = fmaxf(m0, mx0), mn1 = fmaxf(m1, mx1);
        float f0 = __expf(m0 - mn0), f1 = __expf(m1 - mn1);
        m0 = mn0; m1 = mn1;
#pragma unroll
        for (int nd = 0; nd < 8; nd++) {
            pv[nd][0] *= f0; pv[nd][1] *= f0;
            pv[nd][2] *= f1; pv[nd][3] *= f1;
        }

        unsigned pa_hi[4][4], pa_lo[4][4];
        float rs0 = 0.f, rs1 = 0.f;
#pragma unroll
        for (int kt = 0; kt < 4; kt++) {
            float p00 = __expf(sacc[2 * kt][0] - m0);
            float p01 = __expf(sacc[2 * kt][1] - m0);
            float p02 = __expf(sacc[2 * kt][2] - m1);
            float p03 = __expf(sacc[2 * kt][3] - m1);
            float p10 = __expf(sacc[2 * kt + 1][0] - m0);
            float p11 = __expf(sacc[2 * kt + 1][1] - m0);
            float p12 = __expf(sacc[2 * kt + 1][2] - m1);
            float p13 = __expf(sacc[2 * kt + 1][3] - m1);
            rs0 += p00 + p01 + p10 + p11;
            rs1 += p02 + p03 + p12 + p13;
            split_pack(p00, p01, pa_hi[kt][0], pa_lo[kt][0]);
            split_pack(p02, p03, pa_hi[kt][1], pa_lo[kt][1]);
            split_pack(p10, p11, pa_hi[kt][2], pa_lo[kt][2]);
            split_pack(p12, p13, pa_hi[kt][3], pa_lo[kt][3]);
        }
        rs0 += __shfl_xor_sync(0xffffffffu, rs0, 1);
        rs0 += __shfl_xor_sync(0xffffffffu, rs0, 2);
        rs1 += __shfl_xor_sync(0xffffffffu, rs1, 1);
        rs1 += __shfl_xor_sync(0xffffffffu, rs1, 2);
        l0 = l0 * f0 + rs0;
        l1 = l1 * f1 + rs1;

#pragma unroll
        for (int ndp = 0; ndp < 4; ndp++) {
            const int nd = ndp * 2;
            const unsigned vb = nd * 16 + pv_off;
#pragma unroll
            for (int kt = 0; kt < 4; kt++) {
                unsigned bh0, bh1, bh2, bh3, bl0, bl1, bl2, bl3;
                ldsm_x4_t(bh0, bh1, bh2, bh3, vHiA + kt * (16 * ROWB) + vb);
                ldsm_x4_t(bl0, bl1, bl2, bl3, vLoA + kt * (16 * ROWB) + vb);
                mma_bf16(pv[nd],     pa_hi[kt], bh0, bh1);
                mma_bf16(pv[nd],     pa_hi[kt], bl0, bl1);
                mma_bf16(pv[nd],     pa_lo[kt], bh0, bh1);
                mma_bf16(pv[nd + 1], pa_hi[kt], bh2, bh3);
                mma_bf16(pv[nd + 1], pa_hi[kt], bl2, bl3);
                mma_bf16(pv[nd + 1], pa_lo[kt], bh2, bh3);
            }
        }
    }

    float inv0 = 1.f / l0, inv1 = 1.f / l1;
    int bcol = h * Dd + 2 * lr;
    size_t ob0 = ((size_t)b * Tt + rg0) * Ee + bcol;
    size_t ob1 = ((size_t)b * Tt + rg1) * Ee + bcol;
#pragma unroll
    for (int nd = 0; nd < 8; nd++) {
        *(float2*)(g_attnout + ob0 + nd * 8) =
            make_float2(pv[nd][0] * inv0, pv[nd][1] * inv0);
        *(float2*)(g_attnout + ob1 + nd * 8) =
            make_float2(pv[nd][2] * inv1, pv[nd][3] * inv1);
    }
    if (lr == 0) {
        size_t rowbase = (size_t)(b * Hh + h) * Tt + t0 + 16 * w;
        g_rowm[rowbase + lq]     = m0;
        g_rowm[rowbase + lq + 8] = m1;
        g_rowl[rowbase + lq]     = l0;
        g_rowl[rowbase + lq + 8] = l1;
    }
}

// ---------------- normalize raw scores -> softmax weights, in place ----------------
__global__ void normalize_attn(float* __restrict__ attnw)
{
    const size_t n4 = (size_t)Bb * Hh * Tt * Ssq / 4;
    float4* a4 = (float4*)attnw;
    for (size_t i = (size_t)blockIdx.x * blockDim.x + threadIdx.x; i < n4;
         i += (size_t)gridDim.x * blockDim.x) {
        size_t row = (i * 4) / Ssq;
        float m = g_rowm[row];
        float invl = 1.f / g_rowl[row];
        float4 v = a4[i];
        v.x = __expf(v.x - m) * invl;
        v.y = __expf(v.y - m) * invl;
        v.z = __expf(v.z - m) * invl;
        v.w = __expf(v.w - m) * invl;
        a4[i] = v;
    }
}

// ---------------- launch ----------------
extern "C" void kernel_launch(void* const* d_in, const int* in_sizes, int n_in,
                              void* d_out, int out_size)
{
    const float* query = (const float*)d_in[0];
    const float* key   = (const float*)d_in[1];
    const float* value = (const float*)d_in[2];
    const unsigned char* kpm = (const unsigned char*)d_in[3];
    const unsigned char* am  = (const unsigned char*)d_in[4];
    const float* Wq = (const float*)d_in[5];  const float* bq = (const float*)d_in[6];
    const float* Wk = (const float*)d_in[7];  const float* bk = (const float*)d_in[8];
    const float* Wv = (const float*)d_in[9];  const float* bv = (const float*)d_in[10];
    const float* Wo = (const float*)d_in[11]; const float* bo = (const float*)d_in[12];

    float *qp, *kp, *vp, *aop;
    unsigned *ahi, *alo, *whi, *wlo;
    cudaGetSymbolAddress((void**)&qp,  g_q);
    cudaGetSymbolAddress((void**)&kp,  g_k);
    cudaGetSymbolAddress((void**)&vp,  g_v);
    cudaGetSymbolAddress((void**)&aop, g_attnout);
    cudaGetSymbolAddress((void**)&ahi, g_ahi);
    cudaGetSymbolAddress((void**)&alo, g_alo);
    cudaGetSymbolAddress((void**)&whi, g_whi);
    cudaGetSymbolAddress((void**)&wlo, g_wlo);

    const long long OUT_E  = (long long)Bb * Tt * Ee;                  // 4,194,304
    const long long ATTN_E = (long long)Bb * Hh * Tt * (long long)Ssq; // 134,217,728
    float* out_main = nullptr;
    float* out_attn = nullptr;
    if ((long long)out_size >= OUT_E + ATTN_E) {
        out_main = (float*)d_out;
        out_attn = (float*)d_out + OUT_E;
    } else if ((long long)out_size == ATTN_E) {
        out_attn = (float*)d_out;
    } else {
        out_main = (float*)d_out;
    }

    const int A_N2 = BT * Ee / 2;   // 2,097,152 float pairs
    const int W_N2 = Ee * Ee / 2;   // 131,072 float pairs
    dim3 gg(Ee / 128, BT / 128);    // (4, 64)

    // Q projection (head layout, pre-scaled)
    split_bf16<<<2048, 256>>>(query, ahi, alo, A_N2);
    split_bf16<<<512, 256>>>(Wq, whi, wlo, W_N2);
    gemm_bf16_split<<<gg, 256>>>(ahi, alo, whi, wlo, bq, qp, 0.125f, 1);

    // K projection
    split_bf16<<<2048, 256>>>(key, ahi, alo, A_N2);
    split_bf16<<<512, 256>>>(Wk, whi, wlo, W_N2);
    gemm_bf16_split<<<gg, 256>>>(ahi, alo, whi, wlo, bk, kp, 1.0f, 1);

    // V projection
    split_bf16<<<2048, 256>>>(value, ahi, alo, A_N2);
    split_bf16<<<512, 256>>>(Wv, whi, wlo, W_N2);
    gemm_bf16_split<<<gg, 256>>>(ahi, alo, whi, wlo, bv, vp, 1.0f, 1);

    // tensor-core fused attention (LDSM-fed)
    dim3 ag(Tt / AQT, Hh, Bb);  // (16, 8, 4)
    attn_kernel<<<ag, 256>>>(kpm, am, out_attn);

    if (out_attn) normalize_attn<<<2048, 256>>>(out_attn);

    // output projection
    if (out_main) {
        split_bf16<<<2048, 256>>>(aop, ahi, alo, A_N2);
        split_bf16<<<512, 256>>>(Wo, whi, wlo, W_N2);
        gemm_bf16_split<<<gg, 256>>>(ahi, alo, whi, wlo, bo, out_main, 1.0f, 0);
    }
}